// round 1
// baseline (speedup 1.0000x reference)
#include <cuda_runtime.h>
#include <math.h>
#include <float.h>

#define N_UTTS 2048
#define SEQ 50
#define DEMB 300
#define DFILT 64
#define DOUT 100
#define NF 192
#define WIND 10
#define HOPS 3
#define NCLS 7
#define NROWS (N_UTTS - 1)
#define KC 150
#define WPITCH 65

// scratch (device globals: allocation-free)
__device__ float g_sutt[N_UTTS * DOUT];
__device__ float g_wihT[100 * 300];
__device__ float g_whhT[100 * 300];
__device__ float g_membank[(size_t)NROWS * WIND * DOUT];
__device__ float g_eps[NROWS * DOUT];

__device__ __forceinline__ float sigmoidf_(float x) { return 1.0f / (1.0f + expf(-x)); }

// ---------------- GRU weight transpose: wT[k*300 + row] = w[row*100 + k] ----------------
__global__ void transpose_gru_kernel(const float* __restrict__ wih, const float* __restrict__ whh) {
    int i = blockIdx.x * blockDim.x + threadIdx.x;
    if (i < 30000) {
        int row = i / 100, k = i - row * 100;
        g_wihT[k * 300 + row] = wih[i];
        g_whhT[k * 300 + row] = whh[i];
    }
}

// ---------------- Fused embedding-gather + conv + relu + maxpool + tanh transform ----------------
// grid = 2048 blocks (one utterance), 128 threads.
// dyn smem: smE[54*300] | smW[KC*WPITCH] | smF[192] | smR[512]
__global__ void __launch_bounds__(128, 2) conv_encoder_kernel(
    const int* __restrict__ sents, const float* __restrict__ emb,
    const float* __restrict__ w3, const float* __restrict__ b3,
    const float* __restrict__ w4, const float* __restrict__ b4,
    const float* __restrict__ w5, const float* __restrict__ b5,
    const float* __restrict__ trans_w, const float* __restrict__ trans_b)
{
    extern __shared__ float sm[];
    float* smE = sm;                       // 54*300 = 16200
    float* smW = smE + 54 * 300;           // KC*WPITCH = 9750
    float* smF = smW + KC * WPITCH;        // 192
    float* smR = smF + NF;                 // 8*64 = 512
    __shared__ int tok[SEQ];

    const int n = blockIdx.x;
    const int tid = threadIdx.x;
    const int ol = tid & 15;      // o-lane 0..15
    const int tg = tid >> 4;      // t-group 0..7

    if (tid < SEQ) tok[tid] = sents[n * SEQ + tid];
    __syncthreads();
    for (int i = tid; i < 54 * 300; i += 128) {
        if (i < SEQ * 300) {
            int t = i / 300, d = i - t * 300;
            smE[i] = emb[(size_t)tok[t] * 300 + d];
        } else {
            smE[i] = 0.0f;
        }
    }
    __syncthreads();

    const float* Ws[3] = { w3, w4, w5 };
    const float* Bs[3] = { b3, b4, b5 };

    for (int g = 0; g < 3; g++) {
        const int fs = 3 + g;
        const float* __restrict__ wg = Ws[g];
        float acc[4][6];
#pragma unroll
        for (int m = 0; m < 4; m++)
#pragma unroll
            for (int i = 0; i < 6; i++) acc[m][i] = 0.0f;

        for (int j = 0; j < fs; j++) {
            for (int k0 = 0; k0 < 300; k0 += KC) {
                __syncthreads();
                // stage W chunk: smW[kk*WPITCH + o] = wg[o*fs*300 + j*300 + k0 + kk]
                for (int li = tid; li < KC * 64; li += 128) {
                    int o = li / KC, kk = li - o * KC;
                    smW[kk * WPITCH + o] = wg[o * fs * 300 + j * 300 + k0 + kk];
                }
                __syncthreads();
                const float* ep = &smE[(tg * 6 + j) * 300 + k0];
#pragma unroll 2
                for (int kk = 0; kk < KC; kk++) {
                    float w0 = smW[kk * WPITCH + ol];
                    float w1 = smW[kk * WPITCH + ol + 16];
                    float w2 = smW[kk * WPITCH + ol + 32];
                    float w3v = smW[kk * WPITCH + ol + 48];
#pragma unroll
                    for (int i = 0; i < 6; i++) {
                        float e = ep[i * 300 + kk];
                        acc[0][i] = fmaf(w0, e, acc[0][i]);
                        acc[1][i] = fmaf(w1, e, acc[1][i]);
                        acc[2][i] = fmaf(w2, e, acc[2][i]);
                        acc[3][i] = fmaf(w3v, e, acc[3][i]);
                    }
                }
            }
        }
        // max over this thread's valid positions
        const int tmax = SEQ - fs;  // t in [0, tmax]
        float mx[4];
#pragma unroll
        for (int m = 0; m < 4; m++) {
            float v = -FLT_MAX;
#pragma unroll
            for (int i = 0; i < 6; i++) {
                int t = tg * 6 + i;
                if (t <= tmax) v = fmaxf(v, acc[m][i]);
            }
            mx[m] = v;
        }
        __syncthreads();
#pragma unroll
        for (int m = 0; m < 4; m++) smR[tg * 64 + ol + 16 * m] = mx[m];
        __syncthreads();
        if (tid < 64) {
            float mm = smR[tid];
#pragma unroll
            for (int q = 1; q < 8; q++) mm = fmaxf(mm, smR[q * 64 + tid]);
            smF[g * 64 + tid] = fmaxf(mm + Bs[g][tid], 0.0f);
        }
    }
    __syncthreads();
    if (tid < DOUT) {
        float s = trans_b[tid];
        const float* tw = &trans_w[tid * NF];
#pragma unroll 4
        for (int c = 0; c < NF; c++) s = fmaf(smF[c], tw[c], s);
        g_sutt[n * DOUT + tid] = tanhf(s);
    }
}

// ---------------- GRU over 10 steps; rows independent across blocks ----------------
#define GRU_ROWS 16
__global__ void gru_kernel(const float* __restrict__ bih, const float* __restrict__ bhh)
{
    __shared__ float sx[GRU_ROWS * DOUT];
    __shared__ float sh[GRU_ROWS * DOUT];
    __shared__ float sgi[GRU_ROWS * 300];
    __shared__ float sgh[GRU_ROWS * 300];

    const int tid = threadIdx.x;  // 320
    const int b0 = blockIdx.x * GRU_ROWS;

    for (int i = tid; i < GRU_ROWS * DOUT; i += 320) sh[i] = 0.0f;

    for (int s = 0; s < WIND; s++) {
        for (int i = tid; i < GRU_ROWS * DOUT; i += 320) {
            int r = i / DOUT, d = i - r * DOUT;
            int b = b0 + r;
            int src = b + s - (WIND - 1);
            sx[i] = (b < NROWS && src >= 0) ? g_sutt[src * DOUT + d] : 0.0f;
        }
        __syncthreads();
        if (tid < 300) {
            float ai[GRU_ROWS], ah[GRU_ROWS];
#pragma unroll
            for (int r = 0; r < GRU_ROWS; r++) { ai[r] = 0.0f; ah[r] = 0.0f; }
            for (int k = 0; k < DOUT; k++) {
                float wi = g_wihT[k * 300 + tid];
                float wh = g_whhT[k * 300 + tid];
#pragma unroll
                for (int r = 0; r < GRU_ROWS; r++) {
                    ai[r] = fmaf(sx[r * DOUT + k], wi, ai[r]);
                    ah[r] = fmaf(sh[r * DOUT + k], wh, ah[r]);
                }
            }
#pragma unroll
            for (int r = 0; r < GRU_ROWS; r++) {
                sgi[r * 300 + tid] = ai[r];
                sgh[r * 300 + tid] = ah[r];
            }
        }
        __syncthreads();
        for (int i = tid; i < GRU_ROWS * DOUT; i += 320) {
            int r = i / DOUT, d = i - r * DOUT;
            int b = b0 + r;
            if (b < NROWS) {
                float ir  = sgi[r * 300 + d]       + bih[d];
                float iz  = sgi[r * 300 + 100 + d] + bih[100 + d];
                float inn = sgi[r * 300 + 200 + d] + bih[200 + d];
                float hr  = sgh[r * 300 + d]       + bhh[d];
                float hz  = sgh[r * 300 + 100 + d] + bhh[100 + d];
                float hn  = sgh[r * 300 + 200 + d] + bhh[200 + d];
                float rr = sigmoidf_(ir + hr);
                float zz = sigmoidf_(iz + hz);
                float nn = tanhf(inn + rr * hn);
                float hnew = (1.0f - zz) * nn + zz * sh[i];
                sh[i] = hnew;
                g_membank[((size_t)b * WIND + s) * DOUT + d] = sx[i] + hnew;
            }
        }
        __syncthreads();
    }
}

// ---------------- Attention: one warp per row b (0..2046) ----------------
__global__ void attn_kernel(float* __restrict__ attn_out)
{
    int gw = (blockIdx.x * blockDim.x + threadIdx.x) >> 5;
    int lane = threadIdx.x & 31;
    if (gw >= NROWS) return;
    const int b = gw;
    const float* __restrict__ mb = g_membank + (size_t)b * WIND * DOUT;

    float e[4];
#pragma unroll
    for (int m = 0; m < 4; m++) {
        int d = lane + 32 * m;
        e[m] = (d < DOUT) ? g_sutt[(b + 1) * DOUT + d] : 0.0f;
    }

    for (int hop = 0; hop < HOPS; hop++) {
        float lg[WIND];
#pragma unroll
        for (int k = 0; k < WIND; k++) {
            float p = 0.0f;
#pragma unroll
            for (int m = 0; m < 4; m++) {
                int d = lane + 32 * m;
                if (d < DOUT) p = fmaf(e[m], mb[k * DOUT + d], p);
            }
#pragma unroll
            for (int off = 16; off > 0; off >>= 1)
                p += __shfl_xor_sync(0xffffffffu, p, off);
            lg[k] = (b + k - (WIND - 1) >= 0) ? p : -1e10f;
        }
        float mx = lg[0];
#pragma unroll
        for (int k = 1; k < WIND; k++) mx = fmaxf(mx, lg[k]);
        float w[WIND], den = 0.0f;
#pragma unroll
        for (int k = 0; k < WIND; k++) { w[k] = expf(lg[k] - mx); den += w[k]; }
        float inv = 1.0f / den;
#pragma unroll
        for (int k = 0; k < WIND; k++) w[k] *= inv;
        if (lane < WIND)
            attn_out[((size_t)hop * NROWS + b) * WIND + lane] = w[lane];
#pragma unroll
        for (int m = 0; m < 4; m++) {
            int d = lane + 32 * m;
            if (d < DOUT) {
                float add = 0.0f;
#pragma unroll
                for (int k = 0; k < WIND; k++)
                    add = fmaf(w[k], mb[k * DOUT + d], add);
                e[m] += add;
            }
        }
    }
#pragma unroll
    for (int m = 0; m < 4; m++) {
        int d = lane + 32 * m;
        if (d < DOUT) g_eps[b * DOUT + d] = e[m];
    }
}

// ---------------- Classifier: one warp per utterance ----------------
__global__ void cls_kernel(const float* __restrict__ cls_w, const float* __restrict__ cls_b,
                           float* __restrict__ pred)
{
    int gw = (blockIdx.x * blockDim.x + threadIdx.x) >> 5;
    int lane = threadIdx.x & 31;
    if (gw >= N_UTTS) return;
    const int n = gw;
    const float* __restrict__ s = (n == 0) ? g_sutt : (g_eps + (size_t)(n - 1) * DOUT);

    float z[NCLS];
#pragma unroll
    for (int c = 0; c < NCLS; c++) z[c] = 0.0f;
    for (int d = lane; d < DOUT; d += 32) {
        float sv = s[d];
#pragma unroll
        for (int c = 0; c < NCLS; c++) z[c] = fmaf(sv, cls_w[c * DOUT + d], z[c]);
    }
#pragma unroll
    for (int c = 0; c < NCLS; c++) {
#pragma unroll
        for (int off = 16; off > 0; off >>= 1)
            z[c] += __shfl_xor_sync(0xffffffffu, z[c], off);
        z[c] += cls_b[c];
    }
    float mx = z[0];
#pragma unroll
    for (int c = 1; c < NCLS; c++) mx = fmaxf(mx, z[c]);
    float den = 0.0f;
#pragma unroll
    for (int c = 0; c < NCLS; c++) den += expf(z[c] - mx);
    float lse = logf(den);
    if (lane < NCLS) pred[(size_t)n * NCLS + lane] = z[lane] - mx - lse;
}

extern "C" void kernel_launch(void* const* d_in, const int* in_sizes, int n_in,
                              void* d_out, int out_size) {
    const int*   sents   = (const int*)  d_in[0];
    // d_in[1] = lengths (unused by reference)
    const float* emb     = (const float*)d_in[2];
    const float* trans_w = (const float*)d_in[3];
    const float* trans_b = (const float*)d_in[4];
    const float* gru_wih = (const float*)d_in[5];
    const float* gru_whh = (const float*)d_in[6];
    const float* gru_bih = (const float*)d_in[7];
    const float* gru_bhh = (const float*)d_in[8];
    const float* cls_w   = (const float*)d_in[9];
    const float* cls_b   = (const float*)d_in[10];
    const float* w3      = (const float*)d_in[11];
    const float* b3      = (const float*)d_in[12];
    const float* w4      = (const float*)d_in[13];
    const float* b4      = (const float*)d_in[14];
    const float* w5      = (const float*)d_in[15];
    const float* b5      = (const float*)d_in[16];

    float* pred = (float*)d_out;                          // 2048*7
    float* attn = (float*)d_out + (size_t)N_UTTS * NCLS;  // 3*2047*10

    // enable >48KB dyn smem for the conv kernel (idempotent host call)
    static int smem_set = 0;
    const int conv_smem = (54 * 300 + KC * WPITCH + NF + 512) * (int)sizeof(float);
    if (!smem_set) {
        cudaFuncSetAttribute(conv_encoder_kernel,
                             cudaFuncAttributeMaxDynamicSharedMemorySize, conv_smem);
        smem_set = 1;
    }

    transpose_gru_kernel<<<(30000 + 255) / 256, 256>>>(gru_wih, gru_whh);
    conv_encoder_kernel<<<N_UTTS, 128, conv_smem>>>(
        sents, emb, w3, b3, w4, b4, w5, b5, trans_w, trans_b);
    gru_kernel<<<(NROWS + GRU_ROWS - 1) / GRU_ROWS, 320>>>(gru_bih, gru_bhh);
    attn_kernel<<<(NROWS * 32 + 127) / 128, 128>>>(attn);
    cls_kernel<<<(N_UTTS * 32 + 127) / 128, 128>>>(cls_w, cls_b, pred);
}